// round 15
// baseline (speedup 1.0000x reference)
#include <cuda_runtime.h>
#include <cuda_fp16.h>
#include <math.h>
#include <stdint.h>

#define B_   2
#define S_   2048
#define H_   2048
#define NH_  16
#define D_   128
#define M_   (B_*S_)          // 4096 rows for all GEMMs

// ---------------- scratch (static device globals; no allocation) ------------
__device__ __align__(256) __half g_x[(size_t)M_*H_];         // x, fp16
__device__ __align__(256) __half g_w[(size_t)4*H_*H_];       // Wq,Wk,Wv,Wo fp16
__device__ __align__(256) __half g_a[(size_t)M_*H_];         // attn out fp16
__device__ __align__(256) __half g_q[(size_t)B_*NH_*S_*D_];
__device__ __align__(256) __half g_k[(size_t)B_*NH_*S_*D_];
__device__ __align__(256) __half g_v[(size_t)B_*NH_*S_*D_];
__device__ __align__(256) float2 g_rope[(size_t)S_ * 64];    // (cos, sin)

// =========================== helpers ========================================
__device__ __forceinline__ uint32_t smem_u32(const void* p) {
    uint32_t a;
    asm("{ .reg .u64 t; cvta.to.shared.u64 t, %1; cvt.u32.u64 %0, t; }"
        : "=r"(a) : "l"(p));
    return a;
}
__device__ __forceinline__ void ldsm4(uint32_t& r0, uint32_t& r1,
                                      uint32_t& r2, uint32_t& r3, uint32_t a) {
    asm volatile("ldmatrix.sync.aligned.m8n8.x4.shared.b16 {%0,%1,%2,%3}, [%4];"
                 : "=r"(r0), "=r"(r1), "=r"(r2), "=r"(r3) : "r"(a));
}
__device__ __forceinline__ void ldsm4t(uint32_t& r0, uint32_t& r1,
                                       uint32_t& r2, uint32_t& r3, uint32_t a) {
    asm volatile("ldmatrix.sync.aligned.m8n8.x4.trans.shared.b16 {%0,%1,%2,%3}, [%4];"
                 : "=r"(r0), "=r"(r1), "=r"(r2), "=r"(r3) : "r"(a));
}
// fp16 MMA, fp32 accumulate; non-volatile so ptxas may schedule freely.
__device__ __forceinline__ void mma16816(float* c, const uint32_t* a,
                                         const uint32_t* b) {
    asm("mma.sync.aligned.m16n8k16.row.col.f32.f16.f16.f32 "
        "{%0,%1,%2,%3}, {%4,%5,%6,%7}, {%8,%9}, {%0,%1,%2,%3};"
        : "+f"(c[0]), "+f"(c[1]), "+f"(c[2]), "+f"(c[3])
        : "r"(a[0]), "r"(a[1]), "r"(a[2]), "r"(a[3]), "r"(b[0]), "r"(b[1]));
}
__device__ __forceinline__ float ex2(float x) {
    float r;
    asm("ex2.approx.ftz.f32 %0, %1;" : "=f"(r) : "f"(x));
    return r;
}
__device__ __forceinline__ uint32_t pack2h(float a, float b) {
    __half2 hv = __halves2half2(__float2half_rn(a), __float2half_rn(b));
    return *(uint32_t*)&hv;
}
#define CP_ASYNC(sa, ga) \
    asm volatile("cp.async.cg.shared.global [%0], [%1], 16;" :: "r"(sa), "l"(ga))
#define CP_COMMIT() asm volatile("cp.async.commit_group;" ::: "memory")
#define CP_WAIT0()  asm volatile("cp.async.wait_group 0;" ::: "memory")
#define CP_WAIT1()  asm volatile("cp.async.wait_group 1;" ::: "memory")

// ====================== setup kernels =======================================
__global__ void __launch_bounds__(64)
rope_init_kernel()
{
    int s = blockIdx.x, p = threadIdx.x;
    float inv = expf(-(float)p * 0.14391156831212787f); // ln(10000)/64
    float ang = (float)s * inv;
    float sn, cs;
    sincosf(ang, &sn, &cs);
    g_rope[s * 64 + p] = make_float2(cs, sn);
}

// fp32 -> fp16 (single)
__global__ void __launch_bounds__(256)
round_kernel(const float* __restrict__ src, __half* __restrict__ dst, int n)
{
    int i = (blockIdx.x * 256 + threadIdx.x) * 4;
    if (i >= n) return;
    float4 v = *(const float4*)(src + i);
    __half h[4] = {__float2half_rn(v.x), __float2half_rn(v.y),
                   __float2half_rn(v.z), __float2half_rn(v.w)};
    *(uint2*)(dst + i) = *(uint2*)h;
}

// four weight matrices -> fp16, z selects source
__global__ void __launch_bounds__(256)
round4_kernel(const float* __restrict__ s0, const float* __restrict__ s1,
              const float* __restrict__ s2, const float* __restrict__ s3,
              __half* __restrict__ dst, int n)
{
    const int z = blockIdx.y;
    const float* src = (z == 0) ? s0 : (z == 1) ? s1 : (z == 2) ? s2 : s3;
    int i = (blockIdx.x * 256 + threadIdx.x) * 4;
    if (i >= n) return;
    float4 v = *(const float4*)(src + i);
    __half h[4] = {__float2half_rn(v.x), __float2half_rn(v.y),
                   __float2half_rn(v.z), __float2half_rn(v.w)};
    *(uint2*)(dst + (size_t)z * n + i) = *(uint2*)h;
}

// ================== fp16 tensor-core GEMM (mma.sync path) ===================
// C[M,N] = A[M,K] @ W[N,K]^T + bias, K=2048, all-fp16, fp32 accum.
// Block tile 64(M) x 256(N), 8 warps 2x4, warp tile 32x64, **BK=128**
// (16 chunks -> 16 barriers), 2-stage cp.async, 1 CTA/SM (174KB smem).
// Race-safe ordering: wait -> syncthreads -> prefetch(it+1) -> compute(it).
// fused: z=0 Q (RoPE), z=1 K (RoPE), z=2 V. non-fused: fp32 [M,N] out.
#define BKG     128
#define LDSTR   272                      // 128 halfs = 256B + 16B pad
#define B_OFF   (64 * LDSTR)             // 17408
#define STG     (B_OFF + 256 * LDSTR)    // 87040
#define GSMEM   (2 * STG)                // 174080 per CTA

__device__ __forceinline__ void g_load(uint32_t sbase,
    const __half* A0, const __half* B0, int k0, int tid)
{
#pragma unroll
    for (int rep = 0; rep < 4; rep++) {      // A: 64 rows x 16 chunks = 1024
        int idx = tid + rep * 256;
        int row = idx >> 4, c16 = idx & 15;
        CP_ASYNC(sbase + row * LDSTR + c16 * 16,
                 A0 + (size_t)row * H_ + k0 + c16 * 8);
    }
#pragma unroll
    for (int rep = 0; rep < 16; rep++) {     // B: 256 rows x 16 chunks = 4096
        int idx = tid + rep * 256;
        int row = idx >> 4, c16 = idx & 15;
        CP_ASYNC(sbase + B_OFF + row * LDSTR + c16 * 16,
                 B0 + (size_t)row * H_ + k0 + c16 * 8);
    }
}

__global__ void __launch_bounds__(256, 1)
gemm_mma(const __half* __restrict__ Ain, const __half* __restrict__ WB,
         const float* __restrict__ b0, const float* __restrict__ b1,
         const float* __restrict__ b2,
         __half* o0, __half* o1, __half* o2,
         float* out, int fused)
{
    extern __shared__ char sm[];
    const uint32_t smb = smem_u32(sm);
    const int tid  = threadIdx.x;
    const int wid  = tid >> 5, lane = tid & 31;
    const int bm   = blockIdx.y * 64, bn = blockIdx.x * 256;
    const int wm   = (wid >> 2) * 32, wn = (wid & 3) * 64;

    const __half* W = WB;
    const float* bias = b0;
    __half* oh = nullptr;
    int mode = 2;
    if (fused) {
        const int z = blockIdx.z;
        W += (size_t)z * H_ * H_;
        bias = (z == 0) ? b0 : (z == 1) ? b1 : b2;
        oh   = (z == 0) ? o0 : (z == 1) ? o1 : o2;
        mode = (z == 2) ? 0 : 1;
    }

    const __half* A0 = Ain + (size_t)bm * H_;
    const __half* B0 = W   + (size_t)bn * H_;

    float acc[2][8][4];
#pragma unroll
    for (int i = 0; i < 2; i++)
#pragma unroll
        for (int j = 0; j < 8; j++)
#pragma unroll
            for (int q = 0; q < 4; q++) acc[i][j][q] = 0.f;

    const int arow  = (lane & 7) + ((lane >> 3) & 1) * 8;
    const int acoff = ((lane >> 4) & 1) * 16;
    const int krow  = (lane & 7) + ((lane >> 4) & 1) * 8;
    const int kcoff = ((lane >> 3) & 1) * 16;

    g_load(smb, A0, B0, 0, tid);
    CP_COMMIT();

    const int NCH = H_ / BKG;   // 16
    for (int it = 0; it < NCH; it++) {
        CP_WAIT0();             // current stage's data complete
        __syncthreads();        // all warps done with the stage we overwrite
        if (it + 1 < NCH) {
            g_load(smb + ((it + 1) & 1) * STG, A0, B0, (it + 1) * BKG, tid);
            CP_COMMIT();        // loads overlap this chunk's compute
        }

        const uint32_t st = smb + (uint32_t)(it & 1) * STG;
#pragma unroll
        for (int ks = 0; ks < 8; ks++) {
            const int kb = ks * 32;
            uint32_t af[2][4];
#pragma unroll
            for (int mi = 0; mi < 2; mi++) {
                uint32_t off = (uint32_t)((wm + mi * 16 + arow) * LDSTR + kb + acoff);
                ldsm4(af[mi][0], af[mi][1], af[mi][2], af[mi][3], st + off);
            }
#pragma unroll
            for (int nq = 0; nq < 4; nq++) {
                uint32_t off = (uint32_t)((wn + nq * 16 + krow) * LDSTR + kb + kcoff);
                uint32_t b4[4];
                ldsm4(b4[0], b4[1], b4[2], b4[3], st + B_OFF + off);
                mma16816(acc[0][2*nq],   af[0], &b4[0]);
                mma16816(acc[1][2*nq],   af[1], &b4[0]);
                mma16816(acc[0][2*nq+1], af[0], &b4[2]);
                mma16816(acc[1][2*nq+1], af[1], &b4[2]);
            }
        }
    }

    // ------------------------------ epilogue --------------------------------
    const int qrow = lane >> 2;
    const int qcol = (lane & 3) * 2;
#pragma unroll
    for (int mi = 0; mi < 2; mi++) {
#pragma unroll
        for (int half_ = 0; half_ < 2; half_++) {
            const int m  = bm + wm + mi * 16 + qrow + half_ * 8;
            const int sI = m & (S_ - 1);
#pragma unroll
            for (int nj = 0; nj < 8; nj++) {
                const int n0 = bn + wn + nj * 8 + qcol;
                float v0 = acc[mi][nj][half_ * 2 + 0] + bias[n0];
                float v1 = acc[mi][nj][half_ * 2 + 1] + bias[n0 + 1];
                if (mode == 1) {
                    int pr = (n0 & (D_ - 1)) >> 1;
                    float2 cssn = g_rope[sI * 64 + pr];
                    float e = v0, o = v1;
                    v0 = e * cssn.x - o * cssn.y;
                    v1 = o * cssn.x + e * cssn.y;
                }
                if (mode == 2) {
                    *(float2*)(out + (size_t)m * H_ + n0) = make_float2(v0, v1);
                } else {
                    int b = m >> 11;
                    int h = n0 >> 7;
                    int dd = n0 & (D_ - 1);
                    size_t idx = (((size_t)(b * NH_ + h) * S_ + sI) << 7) + dd;
                    *(uint32_t*)(oh + idx) = pack2h(v0, v1);
                }
            }
        }
    }
}

// ================= causal flash attention on tensor cores ===================
// 128 queries/block, 128-key tiles, 8 warps, Q fragments in registers,
// K/V single fp16 in smem, 3-stage cp.async pipeline (prefetch it+2 into
// (it+2)%3 = slot last read at it-1, protected by this iteration's barrier).
// Longest blocks launch first (reversed qt).  (unchanged from R14)
#define KSTR  272
#define ARRB  (128 * KSTR)            // 34816 (K or V, 128 rows)
#define STGB  (2 * ARRB)              // K+V per stage: 69632
#define ASMEM (3 * STGB)              // 208896

__device__ __forceinline__ void load_kv(uint32_t sb,
    const __half* kh, const __half* vh, size_t toff, int tid)
{
    const __half* srcs[2] = {kh + toff, vh + toff};
#pragma unroll
    for (int arr = 0; arr < 2; arr++)
#pragma unroll
        for (int rep = 0; rep < 8; rep++) {       // 128 rows x 16 chunks
            int ch = tid + rep * 256;
            int row = ch >> 4, c = ch & 15;
            CP_ASYNC(sb + arr * ARRB + row * KSTR + c * 16,
                     srcs[arr] + row * D_ + c * 8);
        }
}

__global__ void __launch_bounds__(256, 1)
attn_mma(const __half* __restrict__ Qg, const __half* __restrict__ Kg,
         const __half* __restrict__ Vg, __half* __restrict__ Og)
{
    extern __shared__ char sm[];
    const uint32_t smb = smem_u32(sm);
    const int tid = threadIdx.x, wid = tid >> 5, lane = tid & 31;
    const int qt = (int)(gridDim.x - 1 - blockIdx.x);   // longest first
    const int h = blockIdx.y, b = blockIdx.z;
    const int bh = b * NH_ + h;
    const size_t qoff = ((size_t)bh * S_ + qt * 128) * D_;
    const __half* kb = Kg + (size_t)bh * S_ * D_;
    const __half* vb = Vg + (size_t)bh * S_ * D_;

    // ---- stage Q into slot0; extract fragments to registers ----------------
#pragma unroll
    for (int rep = 0; rep < 8; rep++) {
        int ch = tid + rep * 256;
        int row = ch >> 4, c = ch & 15;
        CP_ASYNC(smb + row * KSTR + c * 16, Qg + qoff + row * D_ + c * 8);
    }
    CP_COMMIT(); CP_WAIT0();
    __syncthreads();

    const int arow  = (lane & 7) + ((lane >> 3) & 1) * 8;
    const int acoff = ((lane >> 4) & 1) * 16;
    uint32_t qf[8][4];
#pragma unroll
    for (int kk = 0; kk < 8; kk++) {
        uint32_t off = (uint32_t)((wid * 16 + arow) * KSTR + kk * 32 + acoff);
        ldsm4(qf[kk][0], qf[kk][1], qf[kk][2], qf[kk][3], smb + off);
    }
    __syncthreads();   // Q staging area free for K/V

    const int NT = qt + 1;                      // 128-key tiles

    load_kv(smb, kb, vb, 0, tid); CP_COMMIT();
    if (NT > 1) { load_kv(smb + STGB, kb, vb, (size_t)128 * D_, tid); }
    CP_COMMIT();   // commit (possibly empty) group so wait-counts line up

    float o[16][4];
#pragma unroll
    for (int nt = 0; nt < 16; nt++)
#pragma unroll
        for (int c = 0; c < 4; c++) o[nt][c] = 0.f;
    float mrow[2] = {-1e30f, -1e30f}, lrow[2] = {0.f, 0.f};
    const float CSc = 0.12752551286084458f;   // log2(e)/sqrt(128)

    const int krow  = (lane & 7) + ((lane >> 4) & 1) * 8;
    const int kcoff = ((lane >> 3) & 1) * 16;

    for (int it = 0; it < NT; it++) {
        if (it == NT - 1) { CP_WAIT0(); } else { CP_WAIT1(); }
        __syncthreads();
        const uint32_t st = smb + (uint32_t)(it % 3) * STGB;

        // ---------------- S = Q @ K^T (128 keys) ----------------------------
        float s[16][4];
#pragma unroll
        for (int nj = 0; nj < 16; nj++)
#pragma unroll
            for (int c = 0; c < 4; c++) s[nj][c] = 0.f;

#pragma unroll
        for (int kk = 0; kk < 8; kk++) {
#pragma unroll
            for (int g = 0; g < 8; g++) {
                uint32_t off = (uint32_t)((g * 16 + krow) * KSTR + kk * 32 + kcoff);
                uint32_t k4[4];
                ldsm4(k4[0], k4[1], k4[2], k4[3], st + off);
                mma16816(s[2*g],   qf[kk], &k4[0]);
                mma16816(s[2*g+1], qf[kk], &k4[2]);
            }
        }

        // ---------------- causal mask (diagonal tile only) ------------------
        if (it == qt) {
            const int q0r = qt * 128 + wid * 16 + (lane >> 2);
            const int kc  = it * 128 + (lane & 3) * 2;
#pragma unroll
            for (int nj = 0; nj < 16; nj++) {
                int kcol = kc + nj * 8;
                if (kcol     > q0r)     s[nj][0] = -1e30f;
                if (kcol + 1 > q0r)     s[nj][1] = -1e30f;
                if (kcol     > q0r + 8) s[nj][2] = -1e30f;
                if (kcol + 1 > q0r + 8) s[nj][3] = -1e30f;
            }
        }

        // ---------------- online softmax (one pass per 128 keys) ------------
        float tm0 = -1e30f, tm1 = -1e30f;
#pragma unroll
        for (int nj = 0; nj < 16; nj++) {
            tm0 = fmaxf(tm0, fmaxf(s[nj][0], s[nj][1]));
            tm1 = fmaxf(tm1, fmaxf(s[nj][2], s[nj][3]));
        }
        tm0 = fmaxf(tm0, __shfl_xor_sync(0xffffffffu, tm0, 1));
        tm0 = fmaxf(tm0, __shfl_xor_sync(0xffffffffu, tm0, 2));
        tm1 = fmaxf(tm1, __shfl_xor_sync(0xffffffffu, tm1, 1));
        tm1 = fmaxf(tm1, __shfl_xor_sync(0xffffffffu, tm1, 2));
        float mn0 = fmaxf(mrow[0], tm0), mn1 = fmaxf(mrow[1], tm1);
        float cor0 = ex2(CSc * (mrow[0] - mn0));
        float cor1 = ex2(CSc * (mrow[1] - mn1));
        mrow[0] = mn0; mrow[1] = mn1;
        float rs0 = 0.f, rs1 = 0.f;
#pragma unroll
        for (int nj = 0; nj < 16; nj++) {
            s[nj][0] = ex2(CSc * (s[nj][0] - mn0)); rs0 += s[nj][0];
            s[nj][1] = ex2(CSc * (s[nj][1] - mn0)); rs0 += s[nj][1];
            s[nj][2] = ex2(CSc * (s[nj][2] - mn1)); rs1 += s[nj][2];
            s[nj][3] = ex2(CSc * (s[nj][3] - mn1)); rs1 += s[nj][3];
        }
        rs0 += __shfl_xor_sync(0xffffffffu, rs0, 1);
        rs0 += __shfl_xor_sync(0xffffffffu, rs0, 2);
        rs1 += __shfl_xor_sync(0xffffffffu, rs1, 1);
        rs1 += __shfl_xor_sync(0xffffffffu, rs1, 2);
        lrow[0] = lrow[0] * cor0 + rs0;
        lrow[1] = lrow[1] * cor1 + rs1;
#pragma unroll
        for (int nt = 0; nt < 16; nt++) {
            o[nt][0] *= cor0; o[nt][1] *= cor0;
            o[nt][2] *= cor1; o[nt][3] *= cor1;
        }

        // ---------------- P -> fp16 a-frags (registers only) ----------------
        uint32_t pf[8][4];
#pragma unroll
        for (int t = 0; t < 8; t++) {
            pf[t][0] = pack2h(s[2*t][0],   s[2*t][1]);
            pf[t][1] = pack2h(s[2*t][2],   s[2*t][3]);
            pf[t][2] = pack2h(s[2*t+1][0], s[2*t+1][1]);
            pf[t][3] = pack2h(s[2*t+1][2], s[2*t+1][3]);
        }

        // ---------------- O += P @ V (128 keys) -----------------------------
#pragma unroll
        for (int t = 0; t < 8; t++) {
#pragma unroll
            for (int nc = 0; nc < 8; nc++) {
                uint32_t off = (uint32_t)((t * 16 + arow) * KSTR + nc * 32 + acoff);
                uint32_t v4[4];
                ldsm4t(v4[0], v4[1], v4[2], v4[3], st + ARRB + off);
                mma16816(o[2*nc],   pf[t], &v4[0]);
                mma16816(o[2*nc+1], pf[t], &v4[2]);
            }
        }

        if (it + 2 < NT) {
            load_kv(smb + (uint32_t)((it + 2) % 3) * STGB,
                    kb, vb, (size_t)(it + 2) * 128 * D_, tid);
            CP_COMMIT();
        }
    }

    // ---------------- epilogue: O/l -> fp16, [b*s, h*d] ---------------------
    const float inv0 = 1.f / lrow[0], inv1 = 1.f / lrow[1];
    const int q0 = qt * 128 + wid * 16 + (lane >> 2);
    const size_t base0 = ((size_t)(b * S_) + q0) * H_ + h * 128;
    const size_t base1 = base0 + (size_t)8 * H_;
#pragma unroll
    for (int nt = 0; nt < 16; nt++) {
        const int col = nt * 8 + (lane & 3) * 2;
        *(uint32_t*)(Og + base0 + col) = pack2h(o[nt][0] * inv0, o[nt][1] * inv0);
        *(uint32_t*)(Og + base1 + col) = pack2h(o[nt][2] * inv1, o[nt][3] * inv1);
    }
}

// ============================================================================
extern "C" void kernel_launch(void* const* d_in, const int* in_sizes, int n_in,
                              void* d_out, int out_size)
{
    const float* x  = (const float*)d_in[0];
    const float* Wq = (const float*)d_in[1];
    const float* bq = (const float*)d_in[2];
    const float* Wk = (const float*)d_in[3];
    const float* bk = (const float*)d_in[4];
    const float* Wv = (const float*)d_in[5];
    const float* bv = (const float*)d_in[6];
    const float* Wo = (const float*)d_in[7];
    const float* bo = (const float*)d_in[8];
    float* out = (float*)d_out;

    __half *xp, *wp, *ap, *qp, *kp, *vp;
    cudaGetSymbolAddress((void**)&xp, g_x);
    cudaGetSymbolAddress((void**)&wp, g_w);
    cudaGetSymbolAddress((void**)&ap, g_a);
    cudaGetSymbolAddress((void**)&qp, g_q);
    cudaGetSymbolAddress((void**)&kp, g_k);
    cudaGetSymbolAddress((void**)&vp, g_v);

    cudaFuncSetAttribute(gemm_mma,
                         cudaFuncAttributeMaxDynamicSharedMemorySize, GSMEM);
    cudaFuncSetAttribute(attn_mma,
                         cudaFuncAttributeMaxDynamicSharedMemorySize, ASMEM);

    const int nX = M_ * H_;
    const int nW = H_ * H_;
    rope_init_kernel<<<S_, 64>>>();
    round_kernel<<<nX / 1024, 256>>>(x, xp, nX);
    round4_kernel<<<dim3(nW / 1024, 4), 256>>>(Wq, Wk, Wv, Wo, wp, nW);

    dim3 gq(H_ / 256, M_ / 64, 3);
    gemm_mma<<<gq, 256, GSMEM>>>(xp, wp, bq, bk, bv,
                                 qp, kp, vp, nullptr, 1);

    attn_mma<<<dim3(S_ / 128, NH_, B_), 256, ASMEM>>>(qp, kp, vp, ap);

    dim3 go(H_ / 256, M_ / 64, 1);
    gemm_mma<<<go, 256, GSMEM>>>(ap, wp + 3*(size_t)nW,
                                 bo, nullptr, nullptr,
                                 nullptr, nullptr, nullptr,
                                 out, 0);
}

// round 16
// speedup vs baseline: 1.1568x; 1.1568x over previous
#include <cuda_runtime.h>
#include <cuda_fp16.h>
#include <math.h>
#include <stdint.h>

#define B_   2
#define S_   2048
#define H_   2048
#define NH_  16
#define D_   128
#define M_   (B_*S_)          // 4096 rows for all GEMMs

// ---------------- scratch (static device globals; no allocation) ------------
__device__ __align__(256) __half g_x[(size_t)M_*H_];         // x, fp16
__device__ __align__(256) __half g_w[(size_t)4*H_*H_];       // Wq,Wk,Wv,Wo fp16
__device__ __align__(256) __half g_a[(size_t)M_*H_];         // attn out fp16
__device__ __align__(256) __half g_q[(size_t)B_*NH_*S_*D_];
__device__ __align__(256) __half g_k[(size_t)B_*NH_*S_*D_];
__device__ __align__(256) __half g_v[(size_t)B_*NH_*S_*D_];
__device__ __align__(256) float2 g_rope[(size_t)S_ * 64];    // (cos, sin)

// =========================== helpers ========================================
__device__ __forceinline__ uint32_t smem_u32(const void* p) {
    uint32_t a;
    asm("{ .reg .u64 t; cvta.to.shared.u64 t, %1; cvt.u32.u64 %0, t; }"
        : "=r"(a) : "l"(p));
    return a;
}
__device__ __forceinline__ void ldsm4(uint32_t& r0, uint32_t& r1,
                                      uint32_t& r2, uint32_t& r3, uint32_t a) {
    asm volatile("ldmatrix.sync.aligned.m8n8.x4.shared.b16 {%0,%1,%2,%3}, [%4];"
                 : "=r"(r0), "=r"(r1), "=r"(r2), "=r"(r3) : "r"(a));
}
__device__ __forceinline__ void ldsm4t(uint32_t& r0, uint32_t& r1,
                                       uint32_t& r2, uint32_t& r3, uint32_t a) {
    asm volatile("ldmatrix.sync.aligned.m8n8.x4.trans.shared.b16 {%0,%1,%2,%3}, [%4];"
                 : "=r"(r0), "=r"(r1), "=r"(r2), "=r"(r3) : "r"(a));
}
// fp16 MMA, fp32 accumulate; non-volatile so ptxas may schedule freely.
__device__ __forceinline__ void mma16816(float* c, const uint32_t* a,
                                         const uint32_t* b) {
    asm("mma.sync.aligned.m16n8k16.row.col.f32.f16.f16.f32 "
        "{%0,%1,%2,%3}, {%4,%5,%6,%7}, {%8,%9}, {%0,%1,%2,%3};"
        : "+f"(c[0]), "+f"(c[1]), "+f"(c[2]), "+f"(c[3])
        : "r"(a[0]), "r"(a[1]), "r"(a[2]), "r"(a[3]), "r"(b[0]), "r"(b[1]));
}
__device__ __forceinline__ float ex2(float x) {
    float r;
    asm("ex2.approx.ftz.f32 %0, %1;" : "=f"(r) : "f"(x));
    return r;
}
__device__ __forceinline__ uint32_t pack2h(float a, float b) {
    __half2 hv = __halves2half2(__float2half_rn(a), __float2half_rn(b));
    return *(uint32_t*)&hv;
}
#define CP_ASYNC(sa, ga) \
    asm volatile("cp.async.cg.shared.global [%0], [%1], 16;" :: "r"(sa), "l"(ga))
#define CP_COMMIT() asm volatile("cp.async.commit_group;" ::: "memory")
#define CP_WAIT0()  asm volatile("cp.async.wait_group 0;" ::: "memory")
#define CP_WAIT1()  asm volatile("cp.async.wait_group 1;" ::: "memory")

// ====================== setup kernels =======================================
__global__ void __launch_bounds__(64)
rope_init_kernel()
{
    int s = blockIdx.x, p = threadIdx.x;
    float inv = expf(-(float)p * 0.14391156831212787f); // ln(10000)/64
    float ang = (float)s * inv;
    float sn, cs;
    sincosf(ang, &sn, &cs);
    g_rope[s * 64 + p] = make_float2(cs, sn);
}

// fused fp32->fp16 rounding: z=0 -> x (n elements into dx),
// z=1..4 -> weight z-1 (nw elements each into dw + (z-1)*nw)
__global__ void __launch_bounds__(256)
round5_kernel(const float* __restrict__ sx,
              const float* __restrict__ s0, const float* __restrict__ s1,
              const float* __restrict__ s2, const float* __restrict__ s3,
              __half* __restrict__ dx, __half* __restrict__ dw,
              int nx, int nw)
{
    const int z = blockIdx.y;
    const float* src;
    __half* dst;
    int n;
    if (z == 0)      { src = sx; dst = dx; n = nx; }
    else             { src = (z == 1) ? s0 : (z == 2) ? s1 : (z == 3) ? s2 : s3;
                       dst = dw + (size_t)(z - 1) * nw; n = nw; }
    int i = (blockIdx.x * 256 + threadIdx.x) * 4;
    if (i >= n) return;
    float4 v = *(const float4*)(src + i);
    __half h[4] = {__float2half_rn(v.x), __float2half_rn(v.y),
                   __float2half_rn(v.z), __float2half_rn(v.w)};
    *(uint2*)(dst + i) = *(uint2*)h;
}

// ================== fp16 tensor-core GEMM (mma.sync path) ===================
// R14 config (measured optimum): BK=64, 64x256 block, warp tile 32x64,
// 2-stage cp.async, 2 CTAs/SM, two barriers/chunk (end barrier protects the
// next iteration's prefetch into the opposite stage).
#define BKG     64
#define LDSTR   144
#define B_OFF   (64 * LDSTR)             // 9216
#define STG     (B_OFF + 256 * LDSTR)    // 46080
#define GSMEM   (2 * STG)                // 92160 per CTA

__device__ __forceinline__ void g_load(uint32_t sbase,
    const __half* A0, const __half* B0, int k0, int tid)
{
#pragma unroll
    for (int rep = 0; rep < 2; rep++) {      // A: 64 rows x 8 chunks = 512
        int idx = tid + rep * 256;
        int row = idx >> 3, c8 = idx & 7;
        CP_ASYNC(sbase + row * LDSTR + c8 * 16,
                 A0 + (size_t)row * H_ + k0 + c8 * 8);
    }
#pragma unroll
    for (int rep = 0; rep < 8; rep++) {      // B: 256 rows x 8 chunks = 2048
        int idx = tid + rep * 256;
        int row = idx >> 3, c8 = idx & 7;
        CP_ASYNC(sbase + B_OFF + row * LDSTR + c8 * 16,
                 B0 + (size_t)row * H_ + k0 + c8 * 8);
    }
}

__global__ void __launch_bounds__(256, 2)
gemm_mma(const __half* __restrict__ Ain, const __half* __restrict__ WB,
         const float* __restrict__ b0, const float* __restrict__ b1,
         const float* __restrict__ b2,
         __half* o0, __half* o1, __half* o2,
         float* out, int fused)
{
    extern __shared__ char sm[];
    const uint32_t smb = smem_u32(sm);
    const int tid  = threadIdx.x;
    const int wid  = tid >> 5, lane = tid & 31;
    const int bm   = blockIdx.y * 64, bn = blockIdx.x * 256;
    const int wm   = (wid >> 2) * 32, wn = (wid & 3) * 64;

    const __half* W = WB;
    const float* bias = b0;
    __half* oh = nullptr;
    int mode = 2;
    if (fused) {
        const int z = blockIdx.z;
        W += (size_t)z * H_ * H_;
        bias = (z == 0) ? b0 : (z == 1) ? b1 : b2;
        oh   = (z == 0) ? o0 : (z == 1) ? o1 : o2;
        mode = (z == 2) ? 0 : 1;
    }

    const __half* A0 = Ain + (size_t)bm * H_;
    const __half* B0 = W   + (size_t)bn * H_;

    float acc[2][8][4];
#pragma unroll
    for (int i = 0; i < 2; i++)
#pragma unroll
        for (int j = 0; j < 8; j++)
#pragma unroll
            for (int q = 0; q < 4; q++) acc[i][j][q] = 0.f;

    const int arow  = (lane & 7) + ((lane >> 3) & 1) * 8;
    const int acoff = ((lane >> 4) & 1) * 16;
    const int krow  = (lane & 7) + ((lane >> 4) & 1) * 8;
    const int kcoff = ((lane >> 3) & 1) * 16;

    g_load(smb, A0, B0, 0, tid);
    CP_COMMIT();

    const int NCH = H_ / BKG;   // 32
    for (int it = 0; it < NCH; it++) {
        if (it + 1 < NCH) {
            g_load(smb + ((it + 1) & 1) * STG, A0, B0, (it + 1) * BKG, tid);
            CP_COMMIT();
            CP_WAIT1();
        } else {
            CP_WAIT0();
        }
        __syncthreads();

        const uint32_t st = smb + (uint32_t)(it & 1) * STG;
#pragma unroll
        for (int ks = 0; ks < 4; ks++) {
            const int kb = ks * 32;
            uint32_t af[2][4];
#pragma unroll
            for (int mi = 0; mi < 2; mi++) {
                uint32_t off = (uint32_t)((wm + mi * 16 + arow) * LDSTR + kb + acoff);
                ldsm4(af[mi][0], af[mi][1], af[mi][2], af[mi][3], st + off);
            }
#pragma unroll
            for (int nq = 0; nq < 4; nq++) {
                uint32_t off = (uint32_t)((wn + nq * 16 + krow) * LDSTR + kb + kcoff);
                uint32_t b4[4];
                ldsm4(b4[0], b4[1], b4[2], b4[3], st + B_OFF + off);
                mma16816(acc[0][2*nq],   af[0], &b4[0]);
                mma16816(acc[1][2*nq],   af[1], &b4[0]);
                mma16816(acc[0][2*nq+1], af[0], &b4[2]);
                mma16816(acc[1][2*nq+1], af[1], &b4[2]);
            }
        }
        __syncthreads();   // protects next iteration's prefetch
    }

    // ------------------------------ epilogue --------------------------------
    const int qrow = lane >> 2;
    const int qcol = (lane & 3) * 2;
#pragma unroll
    for (int mi = 0; mi < 2; mi++) {
#pragma unroll
        for (int half_ = 0; half_ < 2; half_++) {
            const int m  = bm + wm + mi * 16 + qrow + half_ * 8;
            const int sI = m & (S_ - 1);
#pragma unroll
            for (int nj = 0; nj < 8; nj++) {
                const int n0 = bn + wn + nj * 8 + qcol;
                float v0 = acc[mi][nj][half_ * 2 + 0] + bias[n0];
                float v1 = acc[mi][nj][half_ * 2 + 1] + bias[n0 + 1];
                if (mode == 1) {
                    int pr = (n0 & (D_ - 1)) >> 1;
                    float2 cssn = g_rope[sI * 64 + pr];
                    float e = v0, o = v1;
                    v0 = e * cssn.x - o * cssn.y;
                    v1 = o * cssn.x + e * cssn.y;
                }
                if (mode == 2) {
                    *(float2*)(out + (size_t)m * H_ + n0) = make_float2(v0, v1);
                } else {
                    int b = m >> 11;
                    int h = n0 >> 7;
                    int dd = n0 & (D_ - 1);
                    size_t idx = (((size_t)(b * NH_ + h) * S_ + sI) << 7) + dd;
                    *(uint32_t*)(oh + idx) = pack2h(v0, v1);
                }
            }
        }
    }
}

// ================= causal flash attention on tensor cores ===================
// 128 queries/block, 128-key tiles, 8 warps, Q fragments in registers,
// K/V single fp16 in smem, 3-stage cp.async pipeline (prefetch it+2 into
// (it+2)%3 = slot last read at it-1, protected by this iteration's barrier).
// Longest blocks launch first (reversed qt).  (unchanged from R14)
#define KSTR  272
#define ARRB  (128 * KSTR)            // 34816 (K or V, 128 rows)
#define STGB  (2 * ARRB)              // K+V per stage: 69632
#define ASMEM (3 * STGB)              // 208896

__device__ __forceinline__ void load_kv(uint32_t sb,
    const __half* kh, const __half* vh, size_t toff, int tid)
{
    const __half* srcs[2] = {kh + toff, vh + toff};
#pragma unroll
    for (int arr = 0; arr < 2; arr++)
#pragma unroll
        for (int rep = 0; rep < 8; rep++) {       // 128 rows x 16 chunks
            int ch = tid + rep * 256;
            int row = ch >> 4, c = ch & 15;
            CP_ASYNC(sb + arr * ARRB + row * KSTR + c * 16,
                     srcs[arr] + row * D_ + c * 8);
        }
}

__global__ void __launch_bounds__(256, 1)
attn_mma(const __half* __restrict__ Qg, const __half* __restrict__ Kg,
         const __half* __restrict__ Vg, __half* __restrict__ Og)
{
    extern __shared__ char sm[];
    const uint32_t smb = smem_u32(sm);
    const int tid = threadIdx.x, wid = tid >> 5, lane = tid & 31;
    const int qt = (int)(gridDim.x - 1 - blockIdx.x);   // longest first
    const int h = blockIdx.y, b = blockIdx.z;
    const int bh = b * NH_ + h;
    const size_t qoff = ((size_t)bh * S_ + qt * 128) * D_;
    const __half* kb = Kg + (size_t)bh * S_ * D_;
    const __half* vb = Vg + (size_t)bh * S_ * D_;

    // ---- stage Q into slot0; extract fragments to registers ----------------
#pragma unroll
    for (int rep = 0; rep < 8; rep++) {
        int ch = tid + rep * 256;
        int row = ch >> 4, c = ch & 15;
        CP_ASYNC(smb + row * KSTR + c * 16, Qg + qoff + row * D_ + c * 8);
    }
    CP_COMMIT(); CP_WAIT0();
    __syncthreads();

    const int arow  = (lane & 7) + ((lane >> 3) & 1) * 8;
    const int acoff = ((lane >> 4) & 1) * 16;
    uint32_t qf[8][4];
#pragma unroll
    for (int kk = 0; kk < 8; kk++) {
        uint32_t off = (uint32_t)((wid * 16 + arow) * KSTR + kk * 32 + acoff);
        ldsm4(qf[kk][0], qf[kk][1], qf[kk][2], qf[kk][3], smb + off);
    }
    __syncthreads();   // Q staging area free for K/V

    const int NT = qt + 1;                      // 128-key tiles

    load_kv(smb, kb, vb, 0, tid); CP_COMMIT();
    if (NT > 1) { load_kv(smb + STGB, kb, vb, (size_t)128 * D_, tid); }
    CP_COMMIT();   // commit (possibly empty) group so wait-counts line up

    float o[16][4];
#pragma unroll
    for (int nt = 0; nt < 16; nt++)
#pragma unroll
        for (int c = 0; c < 4; c++) o[nt][c] = 0.f;
    float mrow[2] = {-1e30f, -1e30f}, lrow[2] = {0.f, 0.f};
    const float CSc = 0.12752551286084458f;   // log2(e)/sqrt(128)

    const int krow  = (lane & 7) + ((lane >> 4) & 1) * 8;
    const int kcoff = ((lane >> 3) & 1) * 16;

    for (int it = 0; it < NT; it++) {
        if (it == NT - 1) { CP_WAIT0(); } else { CP_WAIT1(); }
        __syncthreads();
        const uint32_t st = smb + (uint32_t)(it % 3) * STGB;

        // ---------------- S = Q @ K^T (128 keys) ----------------------------
        float s[16][4];
#pragma unroll
        for (int nj = 0; nj < 16; nj++)
#pragma unroll
            for (int c = 0; c < 4; c++) s[nj][c] = 0.f;

#pragma unroll
        for (int kk = 0; kk < 8; kk++) {
#pragma unroll
            for (int g = 0; g < 8; g++) {
                uint32_t off = (uint32_t)((g * 16 + krow) * KSTR + kk * 32 + kcoff);
                uint32_t k4[4];
                ldsm4(k4[0], k4[1], k4[2], k4[3], st + off);
                mma16816(s[2*g],   qf[kk], &k4[0]);
                mma16816(s[2*g+1], qf[kk], &k4[2]);
            }
        }

        // ---------------- causal mask (diagonal tile only) ------------------
        if (it == qt) {
            const int q0r = qt * 128 + wid * 16 + (lane >> 2);
            const int kc  = it * 128 + (lane & 3) * 2;
#pragma unroll
            for (int nj = 0; nj < 16; nj++) {
                int kcol = kc + nj * 8;
                if (kcol     > q0r)     s[nj][0] = -1e30f;
                if (kcol + 1 > q0r)     s[nj][1] = -1e30f;
                if (kcol     > q0r + 8) s[nj][2] = -1e30f;
                if (kcol + 1 > q0r + 8) s[nj][3] = -1e30f;
            }
        }

        // ---------------- online softmax (one pass per 128 keys) ------------
        float tm0 = -1e30f, tm1 = -1e30f;
#pragma unroll
        for (int nj = 0; nj < 16; nj++) {
            tm0 = fmaxf(tm0, fmaxf(s[nj][0], s[nj][1]));
            tm1 = fmaxf(tm1, fmaxf(s[nj][2], s[nj][3]));
        }
        tm0 = fmaxf(tm0, __shfl_xor_sync(0xffffffffu, tm0, 1));
        tm0 = fmaxf(tm0, __shfl_xor_sync(0xffffffffu, tm0, 2));
        tm1 = fmaxf(tm1, __shfl_xor_sync(0xffffffffu, tm1, 1));
        tm1 = fmaxf(tm1, __shfl_xor_sync(0xffffffffu, tm1, 2));
        float mn0 = fmaxf(mrow[0], tm0), mn1 = fmaxf(mrow[1], tm1);
        float cor0 = ex2(CSc * (mrow[0] - mn0));
        float cor1 = ex2(CSc * (mrow[1] - mn1));
        mrow[0] = mn0; mrow[1] = mn1;
        float rs0 = 0.f, rs1 = 0.f;
#pragma unroll
        for (int nj = 0; nj < 16; nj++) {
            s[nj][0] = ex2(CSc * (s[nj][0] - mn0)); rs0 += s[nj][0];
            s[nj][1] = ex2(CSc * (s[nj][1] - mn0)); rs0 += s[nj][1];
            s[nj][2] = ex2(CSc * (s[nj][2] - mn1)); rs1 += s[nj][2];
            s[nj][3] = ex2(CSc * (s[nj][3] - mn1)); rs1 += s[nj][3];
        }
        rs0 += __shfl_xor_sync(0xffffffffu, rs0, 1);
        rs0 += __shfl_xor_sync(0xffffffffu, rs0, 2);
        rs1 += __shfl_xor_sync(0xffffffffu, rs1, 1);
        rs1 += __shfl_xor_sync(0xffffffffu, rs1, 2);
        lrow[0] = lrow[0] * cor0 + rs0;
        lrow[1] = lrow[1] * cor1 + rs1;
#pragma unroll
        for (int nt = 0; nt < 16; nt++) {
            o[nt][0] *= cor0; o[nt][1] *= cor0;
            o[nt][2] *= cor1; o[nt][3] *= cor1;
        }

        // ---------------- P -> fp16 a-frags (registers only) ----------------
        uint32_t pf[8][4];
#pragma unroll
        for (int t = 0; t < 8; t++) {
            pf[t][0] = pack2h(s[2*t][0],   s[2*t][1]);
            pf[t][1] = pack2h(s[2*t][2],   s[2*t][3]);
            pf[t][2] = pack2h(s[2*t+1][0], s[2*t+1][1]);
            pf[t][3] = pack2h(s[2*t+1][2], s[2*t+1][3]);
        }

        // ---------------- O += P @ V (128 keys) -----------------------------
#pragma unroll
        for (int t = 0; t < 8; t++) {
#pragma unroll
            for (int nc = 0; nc < 8; nc++) {
                uint32_t off = (uint32_t)((t * 16 + arow) * KSTR + nc * 32 + acoff);
                uint32_t v4[4];
                ldsm4t(v4[0], v4[1], v4[2], v4[3], st + ARRB + off);
                mma16816(o[2*nc],   pf[t], &v4[0]);
                mma16816(o[2*nc+1], pf[t], &v4[2]);
            }
        }

        if (it + 2 < NT) {
            load_kv(smb + (uint32_t)((it + 2) % 3) * STGB,
                    kb, vb, (size_t)(it + 2) * 128 * D_, tid);
            CP_COMMIT();
        }
    }

    // ---------------- epilogue: O/l -> fp16, [b*s, h*d] ---------------------
    const float inv0 = 1.f / lrow[0], inv1 = 1.f / lrow[1];
    const int q0 = qt * 128 + wid * 16 + (lane >> 2);
    const size_t base0 = ((size_t)(b * S_) + q0) * H_ + h * 128;
    const size_t base1 = base0 + (size_t)8 * H_;
#pragma unroll
    for (int nt = 0; nt < 16; nt++) {
        const int col = nt * 8 + (lane & 3) * 2;
        *(uint32_t*)(Og + base0 + col) = pack2h(o[nt][0] * inv0, o[nt][1] * inv0);
        *(uint32_t*)(Og + base1 + col) = pack2h(o[nt][2] * inv1, o[nt][3] * inv1);
    }
}

// ============================================================================
extern "C" void kernel_launch(void* const* d_in, const int* in_sizes, int n_in,
                              void* d_out, int out_size)
{
    const float* x  = (const float*)d_in[0];
    const float* Wq = (const float*)d_in[1];
    const float* bq = (const float*)d_in[2];
    const float* Wk = (const float*)d_in[3];
    const float* bk = (const float*)d_in[4];
    const float* Wv = (const float*)d_in[5];
    const float* bv = (const float*)d_in[6];
    const float* Wo = (const float*)d_in[7];
    const float* bo = (const float*)d_in[8];
    float* out = (float*)d_out;

    __half *xp, *wp, *ap, *qp, *kp, *vp;
    cudaGetSymbolAddress((void**)&xp, g_x);
    cudaGetSymbolAddress((void**)&wp, g_w);
    cudaGetSymbolAddress((void**)&ap, g_a);
    cudaGetSymbolAddress((void**)&qp, g_q);
    cudaGetSymbolAddress((void**)&kp, g_k);
    cudaGetSymbolAddress((void**)&vp, g_v);

    cudaFuncSetAttribute(gemm_mma,
                         cudaFuncAttributeMaxDynamicSharedMemorySize, GSMEM);
    cudaFuncSetAttribute(attn_mma,
                         cudaFuncAttributeMaxDynamicSharedMemorySize, ASMEM);

    const int nX = M_ * H_;
    const int nW = H_ * H_;
    rope_init_kernel<<<S_, 64>>>();
    round5_kernel<<<dim3(nX / 1024, 5), 256>>>(x, Wq, Wk, Wv, Wo, xp, wp, nX, nW);

    dim3 gq(H_ / 256, M_ / 64, 3);
    gemm_mma<<<gq, 256, GSMEM>>>(xp, wp, bq, bk, bv,
                                 qp, kp, vp, nullptr, 1);

    attn_mma<<<dim3(S_ / 128, NH_, B_), 256, ASMEM>>>(qp, kp, vp, ap);

    dim3 go(H_ / 256, M_ / 64, 1);
    gemm_mma<<<go, 256, GSMEM>>>(ap, wp + 3*(size_t)nW,
                                 bo, nullptr, nullptr,
                                 nullptr, nullptr, nullptr,
                                 out, 0);
}